// round 13
// baseline (speedup 1.0000x reference)
#include <cuda_runtime.h>

// Upsampling_68882685493276: 2x nearest-neighbor upsample, fp32
// in : [16, 64, 256, 256] -> out: [16, 64, 512, 512]
//
// R13 = R7..R12 resubmit (none ran: GPU acquisition timeouts, infra-side).
//
// R6 (warp-contiguous stores) + ILP-2.
// Each block handles 4 input rows (512 float2). Thread t loads float2s
//   idx  = blk*512 + t        (rows 0-1 of the chunk)
//   idx2 = idx + 256          (rows 2-3 of the chunk)
// Both LDG.64 issue back-to-back (MLP=2), then 4 STG.128, each perfectly
// warp-contiguous (512B / 16 full sectors):
//   o1 = 2*idx - (idx & 127)   -> rows 2h, 2h+1
//   o2 = o1 + 512              -> second load's row pair (= 2*idx2 - i)
//
// Column invariant: (blk*512) % 128 == 0, so i = idx & 127 = t & 127 for
// both loads; o2 - o1 = 2*256 = 512 exactly.

__global__ __launch_bounds__(256)
void upsample2x_f2x2(const float2* __restrict__ in,
                     float4* __restrict__ out)
{
    int t   = threadIdx.x;
    int idx = blockIdx.x * 512 + t;        // first input float2
    // second input float2 = idx + 256

    // Two independent streaming loads, issued back-to-back (MLP=2).
    float2 v0 = __ldcs(in + idx);
    float2 v1 = __ldcs(in + idx + 256);

    float4 e0 = make_float4(v0.x, v0.x, v0.y, v0.y);
    float4 e1 = make_float4(v1.x, v1.x, v1.y, v1.y);

    int i  = idx & 127;       // input column (float2 units)
    int o1 = 2 * idx - i;     // output float4 index for first load, row 2h
    int o2 = o1 + 512;        // = 2*(idx+256) - i

    __stcs(out + o1,       e0);
    __stcs(out + o1 + 128, e0);
    __stcs(out + o2,       e1);
    __stcs(out + o2 + 128, e1);
}

extern "C" void kernel_launch(void* const* d_in, const int* in_sizes, int n_in,
                              void* d_out, int out_size)
{
    const float2* in  = (const float2*)d_in[0];
    float4*       out = (float4*)d_out;

    int n2     = in_sizes[0] / 2;   // 33,554,432 input float2 (exact)
    int blocks = n2 / 512;          // 65,536 blocks, no tail (256*512 | n2)

    upsample2x_f2x2<<<blocks, 256>>>(in, out);
}